// round 5
// baseline (speedup 1.0000x reference)
#include <cuda_runtime.h>
#include <math.h>

#define NB 4
#define NH 16
#define TT 2048
#define DD 64
#define CC 1024
#define MM (NB*TT)   // 8192
#define PAD 68       // smem row stride (multiple of 4 -> float4-aligned)

// Scratch (no allocations allowed): q,k,v in [B,H,T,D], y in [B,T,C]
__device__ float g_q[NB*NH*TT*DD];
__device__ float g_k[NB*NH*TT*DD];
__device__ float g_v[NB*NH*TT*DD];
__device__ float g_y[MM*CC];

// ---------------------------------------------------------------------------
// Tiled SGEMM: out = A[M,K] @ W[K,N] + bias, M=8192, N=K=1024.
// mode 0: out row-major [M,N]
// mode 1: out permuted to [B,H,T,D] (for q/k/v)
// Tile 128x128, BK=8, 256 threads, 8x8 per-thread micro-tile.
// ---------------------------------------------------------------------------
__global__ __launch_bounds__(256, 2) void sgemm_kernel(
    const float* __restrict__ A, const float* __restrict__ W,
    const float* __restrict__ bias, float* __restrict__ out, int mode)
{
    __shared__ float As[8][128];   // k-major (transposed A tile)
    __shared__ float Bs[8][128];
    const int K = CC, N = CC;
    int tid = threadIdx.x;
    int m0 = blockIdx.y << 7;
    int n0 = blockIdx.x << 7;
    int tr = tid >> 4, tc = tid & 15;

    int arow = tid >> 1;           // 0..127
    int acol = (tid & 1) << 2;     // 0 or 4
    int brow = tid >> 5;           // 0..7
    int bcol = (tid & 31) << 2;    // 0..124

    const float* Ap = A + (size_t)(m0 + arow) * K + acol;
    const float* Bp = W + (size_t)brow * N + n0 + bcol;

    float acc[8][8];
    #pragma unroll
    for (int i = 0; i < 8; i++)
        #pragma unroll
        for (int j = 0; j < 8; j++) acc[i][j] = 0.0f;

    for (int k0 = 0; k0 < K; k0 += 8) {
        float4 av = *(const float4*)(Ap + k0);
        float4 bv = *(const float4*)(Bp + (size_t)k0 * N);
        As[acol+0][arow] = av.x;
        As[acol+1][arow] = av.y;
        As[acol+2][arow] = av.z;
        As[acol+3][arow] = av.w;
        *(float4*)(&Bs[brow][bcol]) = bv;
        __syncthreads();

        #pragma unroll
        for (int kk = 0; kk < 8; kk++) {
            float a[8], b[8];
            *(float4*)(a)     = *(float4*)(&As[kk][tr*8]);
            *(float4*)(a + 4) = *(float4*)(&As[kk][tr*8 + 4]);
            *(float4*)(b)     = *(float4*)(&Bs[kk][tc*8]);
            *(float4*)(b + 4) = *(float4*)(&Bs[kk][tc*8 + 4]);
            #pragma unroll
            for (int i = 0; i < 8; i++)
                #pragma unroll
                for (int j = 0; j < 8; j++)
                    acc[i][j] += a[i] * b[j];
        }
        __syncthreads();
    }

    if (mode == 0) {
        #pragma unroll
        for (int i = 0; i < 8; i++) {
            int row = m0 + tr*8 + i;
            #pragma unroll
            for (int j = 0; j < 8; j++) {
                int col = n0 + tc*8 + j;
                out[(size_t)row * N + col] = acc[i][j] + bias[col];
            }
        }
    } else {
        #pragma unroll
        for (int i = 0; i < 8; i++) {
            int row = m0 + tr*8 + i;
            int b = row >> 11;            // row / 2048
            int t = row & (TT - 1);
            #pragma unroll
            for (int j = 0; j < 8; j++) {
                int col = n0 + tc*8 + j;
                int h = col >> 6, d = col & 63;
                out[((size_t)(((b << 4) + h) * TT + t) << 6) + d] = acc[i][j] + bias[col];
            }
        }
    }
}

// ---------------------------------------------------------------------------
// Flash attention (fp32, online softmax).
// Grid: (T/64 query blocks, B*H). 256 threads: (ty,tx) in 16x16, each owns a
// 4x4 micro-tile of the 64x64 S/P tile and 4 query rows x 4 head dims of O.
// Q/K stored k-major, V s-major, rows padded to PAD=68 floats so every
// float4 access is 16B-aligned (PAD=65 trapped with misaligned address).
// Causal: only key blocks jb <= qb visited; diagonal block masked in-register.
// ---------------------------------------------------------------------------
__global__ __launch_bounds__(256, 2) void attn_kernel(float* __restrict__ y)
{
    extern __shared__ float sm[];
    float* Qs = sm;                 // [64][PAD], Qs[k][t]
    float* Ks = sm + 64*PAD;        // [64][PAD], Ks[k][s]
    float* Vs = sm + 2*64*PAD;      // [64][PAD], Vs[s][d]
    float* Ps = sm + 3*64*PAD;      // [64][PAD], Ps[t][s]

    int qb = blockIdx.x, bh = blockIdx.y;
    int tid = threadIdx.x;
    int ty = tid >> 4, tx = tid & 15;

    const float* Qg  = g_q + ((size_t)bh * TT + (size_t)qb * 64) * 64;
    const float* Kg0 = g_k + (size_t)bh * TT * 64;
    const float* Vg0 = g_v + (size_t)bh * TT * 64;

    #pragma unroll
    for (int i = 0; i < 16; i++) {
        int idx = tid + (i << 8);
        int t = idx >> 6, d = idx & 63;
        Qs[d*PAD + t] = Qg[idx];
    }

    float m_i[4], l_i[4], o[4][4];
    #pragma unroll
    for (int i = 0; i < 4; i++) {
        m_i[i] = -1e30f; l_i[i] = 0.0f;
        #pragma unroll
        for (int j = 0; j < 4; j++) o[i][j] = 0.0f;
    }

    for (int jb = 0; jb <= qb; jb++) {
        const float* Kg = Kg0 + (size_t)jb * 64 * 64;
        const float* Vg = Vg0 + (size_t)jb * 64 * 64;
        __syncthreads();   // prior iteration's Ks/Vs/Ps reads done (also covers Q load)
        #pragma unroll
        for (int i = 0; i < 16; i++) {
            int idx = tid + (i << 8);
            int s = idx >> 6, d = idx & 63;
            Ks[d*PAD + s] = Kg[idx];
            Vs[s*PAD + d] = Vg[idx];
        }
        __syncthreads();

        // S = Q @ K^T
        float sv[4][4];
        #pragma unroll
        for (int i = 0; i < 4; i++)
            #pragma unroll
            for (int j = 0; j < 4; j++) sv[i][j] = 0.0f;

        #pragma unroll 8
        for (int k = 0; k < 64; k++) {
            float4 qv = *(float4*)(&Qs[k*PAD + (ty << 2)]);
            float4 kv = *(float4*)(&Ks[k*PAD + (tx << 2)]);
            float q[4] = {qv.x, qv.y, qv.z, qv.w};
            float kr[4] = {kv.x, kv.y, kv.z, kv.w};
            #pragma unroll
            for (int i = 0; i < 4; i++)
                #pragma unroll
                for (int j = 0; j < 4; j++)
                    sv[i][j] += q[i] * kr[j];
        }

        #pragma unroll
        for (int i = 0; i < 4; i++)
            #pragma unroll
            for (int j = 0; j < 4; j++) sv[i][j] *= 0.125f;  // 1/sqrt(64)

        if (jb == qb) {
            #pragma unroll
            for (int i = 0; i < 4; i++)
                #pragma unroll
                for (int j = 0; j < 4; j++)
                    if (((tx << 2) + j) > ((ty << 2) + i)) sv[i][j] = -1e30f;
        }

        // online softmax, row stats reduced across the 16 tx lanes
        #pragma unroll
        for (int i = 0; i < 4; i++) {
            float rm = fmaxf(fmaxf(sv[i][0], sv[i][1]), fmaxf(sv[i][2], sv[i][3]));
            rm = fmaxf(rm, __shfl_xor_sync(0xffffffffu, rm, 1));
            rm = fmaxf(rm, __shfl_xor_sync(0xffffffffu, rm, 2));
            rm = fmaxf(rm, __shfl_xor_sync(0xffffffffu, rm, 4));
            rm = fmaxf(rm, __shfl_xor_sync(0xffffffffu, rm, 8));
            float mn = fmaxf(m_i[i], rm);
            float corr = __expf(m_i[i] - mn);
            m_i[i] = mn;
            float p0 = __expf(sv[i][0] - mn);
            float p1 = __expf(sv[i][1] - mn);
            float p2 = __expf(sv[i][2] - mn);
            float p3 = __expf(sv[i][3] - mn);
            float rs = p0 + p1 + p2 + p3;
            rs += __shfl_xor_sync(0xffffffffu, rs, 1);
            rs += __shfl_xor_sync(0xffffffffu, rs, 2);
            rs += __shfl_xor_sync(0xffffffffu, rs, 4);
            rs += __shfl_xor_sync(0xffffffffu, rs, 8);
            l_i[i] = l_i[i] * corr + rs;
            #pragma unroll
            for (int j = 0; j < 4; j++) o[i][j] *= corr;
            *(float4*)(&Ps[((ty << 2) + i) * PAD + (tx << 2)]) = make_float4(p0, p1, p2, p3);
        }
        __syncthreads();

        // O += P @ V
        #pragma unroll 8
        for (int s = 0; s < 64; s++) {
            float4 vv = *(float4*)(&Vs[s*PAD + (tx << 2)]);
            #pragma unroll
            for (int i = 0; i < 4; i++) {
                float pi = Ps[((ty << 2) + i) * PAD + s];
                o[i][0] += pi * vv.x;
                o[i][1] += pi * vv.y;
                o[i][2] += pi * vv.z;
                o[i][3] += pi * vv.w;
            }
        }
    }

    int b = bh >> 4, h = bh & 15;
    #pragma unroll
    for (int i = 0; i < 4; i++) {
        int t = (qb << 6) + (ty << 2) + i;
        float inv = 1.0f / l_i[i];
        float4 ov = make_float4(o[i][0]*inv, o[i][1]*inv, o[i][2]*inv, o[i][3]*inv);
        *(float4*)(&y[((size_t)(b * TT + t) << 10) + (h << 6) + (tx << 2)]) = ov;
    }
}

// ---------------------------------------------------------------------------

extern "C" void kernel_launch(void* const* d_in, const int* in_sizes, int n_in,
                              void* d_out, int out_size)
{
    (void)in_sizes; (void)n_in; (void)out_size;
    const float* x  = (const float*)d_in[0];
    const float* Wq = (const float*)d_in[1];
    const float* bq = (const float*)d_in[2];
    const float* Wk = (const float*)d_in[3];
    const float* bk = (const float*)d_in[4];
    const float* Wv = (const float*)d_in[5];
    const float* bv = (const float*)d_in[6];
    const float* Wp = (const float*)d_in[7];
    const float* bp = (const float*)d_in[8];

    float *qp, *kp, *vp, *yp;
    cudaGetSymbolAddress((void**)&qp, g_q);
    cudaGetSymbolAddress((void**)&kp, g_k);
    cudaGetSymbolAddress((void**)&vp, g_v);
    cudaGetSymbolAddress((void**)&yp, g_y);

    const int attn_smem = 4 * 64 * PAD * 4;  // 69632 B
    cudaFuncSetAttribute(attn_kernel, cudaFuncAttributeMaxDynamicSharedMemorySize, attn_smem);

    dim3 gg(CC / 128, MM / 128);  // (8, 64)
    sgemm_kernel<<<gg, 256>>>(x, Wq, bq, qp, 1);
    sgemm_kernel<<<gg, 256>>>(x, Wk, bk, kp, 1);
    sgemm_kernel<<<gg, 256>>>(x, Wv, bv, vp, 1);
    attn_kernel<<<dim3(TT / 64, NB * NH), 256, attn_smem>>>(yp);
    sgemm_kernel<<<gg, 256>>>(yp, Wp, bp, (float*)d_out, 0);
}

// round 7
// speedup vs baseline: 1.2618x; 1.2618x over previous
#include <cuda_runtime.h>
#include <cuda_bf16.h>
#include <math.h>

#define NB 4
#define NH 16
#define TT 2048
#define DD 64
#define CC 1024
#define MM (NB*TT)   // 8192
#define PAD 68       // attn smem row stride (float4-aligned)

#define SROW 24      // GEMM smem row stride in bf16 (48B: conflict-free frags + aligned uint4 stores)

// Scratch (no allocations allowed): q,k,v in [B,H,T,D], y in [B,T,C]
__device__ float g_q[NB*NH*TT*DD];
__device__ float g_k[NB*NH*TT*DD];
__device__ float g_v[NB*NH*TT*DD];
__device__ float g_y[MM*CC];

// ---------------------------------------------------------------------------
// Split-precision bf16 GEMM: out = A[M,1024] @ W[1024,1024] + bias.
// x = hi + lo (both bf16); acc = hi*hi + hi*lo + lo*hi in fp32 (3 mma passes).
// Tile 128x128x16, 256 thr, 8 warps (2m x 4n), warp tile 64x32, m16n8k16.
// mode 0: out row-major [M,N]; mode 1: out permuted to [B,H,T,D].
// ---------------------------------------------------------------------------
__device__ __forceinline__ void pack_split(float x0, float x1, unsigned& h, unsigned& l)
{
    __nv_bfloat16 h0 = __float2bfloat16(x0);
    __nv_bfloat16 h1 = __float2bfloat16(x1);
    __nv_bfloat16 l0 = __float2bfloat16(x0 - __bfloat162float(h0));
    __nv_bfloat16 l1 = __float2bfloat16(x1 - __bfloat162float(h1));
    h = (unsigned)__bfloat16_as_ushort(h0) | ((unsigned)__bfloat16_as_ushort(h1) << 16);
    l = (unsigned)__bfloat16_as_ushort(l0) | ((unsigned)__bfloat16_as_ushort(l1) << 16);
}

__device__ __forceinline__ void mma_bf16(float* c, const unsigned* a, unsigned b0, unsigned b1)
{
    asm volatile(
        "mma.sync.aligned.m16n8k16.row.col.f32.bf16.bf16.f32 "
        "{%0,%1,%2,%3}, {%4,%5,%6,%7}, {%8,%9}, {%0,%1,%2,%3};\n"
        : "+f"(c[0]), "+f"(c[1]), "+f"(c[2]), "+f"(c[3])
        : "r"(a[0]), "r"(a[1]), "r"(a[2]), "r"(a[3]), "r"(b0), "r"(b1));
}

__global__ __launch_bounds__(256, 1) void gemm_split_kernel(
    const float* __restrict__ A, const float* __restrict__ W,
    const float* __restrict__ bias, float* __restrict__ out, int mode)
{
    __shared__ unsigned short As_hi[128*SROW], As_lo[128*SROW];
    __shared__ unsigned short Bs_hi[128*SROW], Bs_lo[128*SROW];

    const int K = CC, N = CC;
    int tid  = threadIdx.x;
    int warp = tid >> 5, lane = tid & 31;
    int g = lane >> 2, tg = lane & 3;
    int wm = (warp >> 2) << 6;   // 0 / 64
    int wn = (warp & 3) << 5;    // 0,32,64,96
    int m0 = blockIdx.y << 7, n0 = blockIdx.x << 7;

    int rld = tid & 127;         // row (A) / col (B) this thread loads
    int kh  = tid >> 7;          // 0/1: which 8-wide k half

    const float* Ap = A + (size_t)(m0 + rld) * K + kh * 8;
    const float* Bp = W + (size_t)(kh * 8) * N + n0 + rld;

    float c[4][4][4];
    #pragma unroll
    for (int mf = 0; mf < 4; mf++)
        #pragma unroll
        for (int nf = 0; nf < 4; nf++)
            #pragma unroll
            for (int i = 0; i < 4; i++) c[mf][nf][i] = 0.0f;

    float ar[8], br[8];
    // prologue: k0 = 0
    {
        float4 v0 = *(const float4*)(Ap);
        float4 v1 = *(const float4*)(Ap + 4);
        ar[0]=v0.x; ar[1]=v0.y; ar[2]=v0.z; ar[3]=v0.w;
        ar[4]=v1.x; ar[5]=v1.y; ar[6]=v1.z; ar[7]=v1.w;
        #pragma unroll
        for (int kk = 0; kk < 8; kk++) br[kk] = Bp[(size_t)kk * N];
    }

    #pragma unroll 1
    for (int it = 0; it < K / 16; it++) {
        // convert staged regs -> smem (hi/lo bf16), conflict-free uint4 stores
        {
            unsigned ph[4], pl[4];
            #pragma unroll
            for (int i = 0; i < 4; i++) pack_split(ar[2*i], ar[2*i+1], ph[i], pl[i]);
            *(uint4*)&As_hi[rld*SROW + kh*8] = make_uint4(ph[0], ph[1], ph[2], ph[3]);
            *(uint4*)&As_lo[rld*SROW + kh*8] = make_uint4(pl[0], pl[1], pl[2], pl[3]);
            #pragma unroll
            for (int i = 0; i < 4; i++) pack_split(br[2*i], br[2*i+1], ph[i], pl[i]);
            *(uint4*)&Bs_hi[rld*SROW + kh*8] = make_uint4(ph[0], ph[1], ph[2], ph[3]);
            *(uint4*)&Bs_lo[rld*SROW + kh*8] = make_uint4(pl[0], pl[1], pl[2], pl[3]);
        }
        __syncthreads();

        // prefetch next k-tile into regs (overlaps with mma below)
        if (it + 1 < K / 16) {
            int k0n = (it + 1) * 16;
            float4 v0 = *(const float4*)(Ap + k0n);
            float4 v1 = *(const float4*)(Ap + k0n + 4);
            ar[0]=v0.x; ar[1]=v0.y; ar[2]=v0.z; ar[3]=v0.w;
            ar[4]=v1.x; ar[5]=v1.y; ar[6]=v1.z; ar[7]=v1.w;
            #pragma unroll
            for (int kk = 0; kk < 8; kk++) br[kk] = Bp[(size_t)(k0n + kk) * N];
        }

        // A fragments (hi & lo) for 4 m-frags
        unsigned ahi[4][4], alo[4][4];
        #pragma unroll
        for (int mf = 0; mf < 4; mf++) {
            int r = wm + mf*16 + g;
            int b0 = r * SROW, b8 = (r + 8) * SROW;
            ahi[mf][0] = *(const unsigned*)&As_hi[b0 + 2*tg];
            ahi[mf][1] = *(const unsigned*)&As_hi[b8 + 2*tg];
            ahi[mf][2] = *(const unsigned*)&As_hi[b0 + 2*tg + 8];
            ahi[mf][3] = *(const unsigned*)&As_hi[b8 + 2*tg + 8];
            alo[mf][0] = *(const unsigned*)&As_lo[b0 + 2*tg];
            alo[mf][1] = *(const unsigned*)&As_lo[b8 + 2*tg];
            alo[mf][2] = *(const unsigned*)&As_lo[b0 + 2*tg + 8];
            alo[mf][3] = *(const unsigned*)&As_lo[b8 + 2*tg + 8];
        }
        #pragma unroll
        for (int nf = 0; nf < 4; nf++) {
            int cb = (wn + nf*8 + g) * SROW;
            unsigned bh0 = *(const unsigned*)&Bs_hi[cb + 2*tg];
            unsigned bh1 = *(const unsigned*)&Bs_hi[cb + 2*tg + 8];
            unsigned bl0 = *(const unsigned*)&Bs_lo[cb + 2*tg];
            unsigned bl1 = *(const unsigned*)&Bs_lo[cb + 2*tg + 8];
            #pragma unroll
            for (int mf = 0; mf < 4; mf++) {
                mma_bf16(c[mf][nf], ahi[mf], bh0, bh1);
                mma_bf16(c[mf][nf], ahi[mf], bl0, bl1);
                mma_bf16(c[mf][nf], alo[mf], bh0, bh1);
            }
        }
        __syncthreads();
    }

    // epilogue
    #pragma unroll
    for (int mf = 0; mf < 4; mf++) {
        #pragma unroll
        for (int nf = 0; nf < 4; nf++) {
            int r  = m0 + wm + mf*16 + g;
            int cc = n0 + wn + nf*8 + 2*tg;
            float2 bb = *(const float2*)&bias[cc];
            float2 p0 = make_float2(c[mf][nf][0] + bb.x, c[mf][nf][1] + bb.y);
            float2 p1 = make_float2(c[mf][nf][2] + bb.x, c[mf][nf][3] + bb.y);
            if (mode == 0) {
                *(float2*)&out[(size_t)r * N + cc]       = p0;
                *(float2*)&out[(size_t)(r + 8) * N + cc] = p1;
            } else {
                int h = cc >> 6, d = cc & 63;
                int b1 = r >> 11, t1 = r & (TT - 1);
                *(float2*)&out[((size_t)(((b1 << 4) + h) * TT + t1) << 6) + d] = p0;
                int r2 = r + 8;
                int b2 = r2 >> 11, t2 = r2 & (TT - 1);
                *(float2*)&out[((size_t)(((b2 << 4) + h) * TT + t2) << 6) + d] = p1;
            }
        }
    }
}

// ---------------------------------------------------------------------------
// Flash attention (fp32, online softmax) — unchanged from R5 (passing).
// ---------------------------------------------------------------------------
__global__ __launch_bounds__(256, 2) void attn_kernel(float* __restrict__ y)
{
    extern __shared__ float sm[];
    float* Qs = sm;                 // [64][PAD]
    float* Ks = sm + 64*PAD;
    float* Vs = sm + 2*64*PAD;
    float* Ps = sm + 3*64*PAD;

    int qb = blockIdx.x, bh = blockIdx.y;
    int tid = threadIdx.x;
    int ty = tid >> 4, tx = tid & 15;

    const float* Qg  = g_q + ((size_t)bh * TT + (size_t)qb * 64) * 64;
    const float* Kg0 = g_k + (size_t)bh * TT * 64;
    const float* Vg0 = g_v + (size_t)bh * TT * 64;

    #pragma unroll
    for (int i = 0; i < 16; i++) {
        int idx = tid + (i << 8);
        int t = idx >> 6, d = idx & 63;
        Qs[d*PAD + t] = Qg[idx];
    }

    float m_i[4], l_i[4], o[4][4];
    #pragma unroll
    for (int i = 0; i < 4; i++) {
        m_i[i] = -1e30f; l_i[i] = 0.0f;
        #pragma unroll
        for (int j = 0; j < 4; j++) o[i][j] = 0.0f;
    }

    for (int jb = 0; jb <= qb; jb++) {
        const float* Kg = Kg0 + (size_t)jb * 64 * 64;
        const float* Vg = Vg0 + (size_t)jb * 64 * 64;
        __syncthreads();
        #pragma unroll
        for (int i = 0; i < 16; i++) {
            int idx = tid + (i << 8);
            int s = idx >> 6, d = idx & 63;
            Ks[d*PAD + s] = Kg[idx];
            Vs[s*PAD + d] = Vg[idx];
        }
        __syncthreads();

        float sv[4][4];
        #pragma unroll
        for (int i = 0; i < 4; i++)
            #pragma unroll
            for (int j = 0; j < 4; j++) sv[i][j] = 0.0f;

        #pragma unroll 8
        for (int k = 0; k < 64; k++) {
            float4 qv = *(float4*)(&Qs[k*PAD + (ty << 2)]);
            float4 kv = *(float4*)(&Ks[k*PAD + (tx << 2)]);
            float q[4] = {qv.x, qv.y, qv.z, qv.w};
            float kr[4] = {kv.x, kv.y, kv.z, kv.w};
            #pragma unroll
            for (int i = 0; i < 4; i++)
                #pragma unroll
                for (int j = 0; j < 4; j++)
                    sv[i][j] += q[i] * kr[j];
        }

        #pragma unroll
        for (int i = 0; i < 4; i++)
            #pragma unroll
            for (int j = 0; j < 4; j++) sv[i][j] *= 0.125f;

        if (jb == qb) {
            #pragma unroll
            for (int i = 0; i < 4; i++)
                #pragma unroll
                for (int j = 0; j < 4; j++)
                    if (((tx << 2) + j) > ((ty << 2) + i)) sv[i][j] = -1e30f;
        }

        #pragma unroll
        for (int i = 0; i < 4; i++) {
            float rm = fmaxf(fmaxf(sv[i][0], sv[i][1]), fmaxf(sv[i][2], sv[i][3]));
            rm = fmaxf(rm, __shfl_xor_sync(0xffffffffu, rm, 1));
            rm = fmaxf(rm, __shfl_xor_sync(0xffffffffu, rm, 2));
            rm = fmaxf(rm, __shfl_xor_sync(0xffffffffu, rm, 4));
            rm = fmaxf(rm, __shfl_xor_sync(0xffffffffu, rm, 8));
            float mn = fmaxf(m_i[i], rm);
            float corr = __expf(m_i[i] - mn);
            m_i[i] = mn;
            float p0 = __expf(sv[i][0] - mn);
            float p1 = __expf(sv[i][1] - mn);
            float p2 = __expf(sv[i][2] - mn);
            float p3 = __expf(sv[i][3] - mn);
            float rs = p0 + p1 + p2 + p3;
            rs += __shfl_xor_sync(0xffffffffu, rs, 1);
            rs += __shfl_xor_sync(0xffffffffu, rs, 2);
            rs += __shfl_xor_sync(0xffffffffu, rs, 4);
            rs += __shfl_xor_sync(0xffffffffu, rs, 8);
            l_i[i] = l_i[i] * corr + rs;
            #pragma unroll
            for (int j = 0; j < 4; j++) o[i][j] *= corr;
            *(float4*)(&Ps[((ty << 2) + i) * PAD + (tx << 2)]) = make_float4(p0, p1, p2, p3);
        }
        __syncthreads();

        #pragma unroll 8
        for (int s = 0; s < 64; s++) {
            float4 vv = *(float4*)(&Vs[s*PAD + (tx << 2)]);
            #pragma unroll
            for (int i = 0; i < 4; i++) {
                float pi = Ps[((ty << 2) + i) * PAD + s];
                o[i][0] += pi * vv.x;
                o[i][1] += pi * vv.y;
                o[i][2] += pi * vv.z;
                o[i][3] += pi * vv.w;
            }
        }
    }

    int b = bh >> 4, h = bh & 15;
    #pragma unroll
    for (int i = 0; i < 4; i++) {
        int t = (qb << 6) + (ty << 2) + i;
        float inv = 1.0f / l_i[i];
        float4 ov = make_float4(o[i][0]*inv, o[i][1]*inv, o[i][2]*inv, o[i][3]*inv);
        *(float4*)(&y[((size_t)(b * TT + t) << 10) + (h << 6) + (tx << 2)]) = ov;
    }
}

// ---------------------------------------------------------------------------

extern "C" void kernel_launch(void* const* d_in, const int* in_sizes, int n_in,
                              void* d_out, int out_size)
{
    (void)in_sizes; (void)n_in; (void)out_size;
    const float* x  = (const float*)d_in[0];
    const float* Wq = (const float*)d_in[1];
    const float* bq = (const float*)d_in[2];
    const float* Wk = (const float*)d_in[3];
    const float* bk = (const float*)d_in[4];
    const float* Wv = (const float*)d_in[5];
    const float* bv = (const float*)d_in[6];
    const float* Wp = (const float*)d_in[7];
    const float* bp = (const float*)d_in[8];

    float *qp, *kp, *vp, *yp;
    cudaGetSymbolAddress((void**)&qp, g_q);
    cudaGetSymbolAddress((void**)&kp, g_k);
    cudaGetSymbolAddress((void**)&vp, g_v);
    cudaGetSymbolAddress((void**)&yp, g_y);

    const int attn_smem = 4 * 64 * PAD * 4;  // 69632 B
    cudaFuncSetAttribute(attn_kernel, cudaFuncAttributeMaxDynamicSharedMemorySize, attn_smem);

    dim3 gg(CC / 128, MM / 128);  // (8, 64)
    gemm_split_kernel<<<gg, 256>>>(x, Wq, bq, qp, 1);
    gemm_split_kernel<<<gg, 256>>>(x, Wk, bk, kp, 1);
    gemm_split_kernel<<<gg, 256>>>(x, Wv, bv, vp, 1);
    attn_kernel<<<dim3(TT / 64, NB * NH), 256, attn_smem>>>(yp);
    gemm_split_kernel<<<gg, 256>>>(yp, Wp, bp, (float*)d_out, 0);
}

// round 8
// speedup vs baseline: 2.1782x; 1.7263x over previous
#include <cuda_runtime.h>
#include <cuda_bf16.h>
#include <math.h>

#define NB 4
#define NH 16
#define TT 2048
#define DD 64
#define CC 1024
#define MM (NB*TT)   // 8192
#define SROW 24      // gemm smem row stride (bf16)
#define AROW 72      // attn smem row stride (bf16): 144B rows, 16B-aligned, ldmatrix conflict-free

// ---- device scratch (no allocs allowed) ----
__device__ __nv_bfloat16 g_xh[MM*CC],  g_xl[MM*CC];
__device__ __nv_bfloat16 g_wth[4*CC*CC], g_wtl[4*CC*CC];   // transposed [N][K] per weight
__device__ __nv_bfloat16 g_qh[MM*CC],  g_ql[MM*CC];
__device__ __nv_bfloat16 g_kh[MM*CC],  g_kl[MM*CC];
__device__ __nv_bfloat16 g_vh[MM*CC],  g_vl[MM*CC];
__device__ __nv_bfloat16 g_yh[MM*CC],  g_yl[MM*CC];

// ---- helpers ----
__device__ __forceinline__ void pack_split(float x0, float x1, unsigned& h, unsigned& l)
{
    __nv_bfloat16 h0 = __float2bfloat16(x0);
    __nv_bfloat16 h1 = __float2bfloat16(x1);
    __nv_bfloat16 l0 = __float2bfloat16(x0 - __bfloat162float(h0));
    __nv_bfloat16 l1 = __float2bfloat16(x1 - __bfloat162float(h1));
    h = (unsigned)__bfloat16_as_ushort(h0) | ((unsigned)__bfloat16_as_ushort(h1) << 16);
    l = (unsigned)__bfloat16_as_ushort(l0) | ((unsigned)__bfloat16_as_ushort(l1) << 16);
}

__device__ __forceinline__ void mma_bf16(float* c, const unsigned* a, unsigned b0, unsigned b1)
{
    asm volatile(
        "mma.sync.aligned.m16n8k16.row.col.f32.bf16.bf16.f32 "
        "{%0,%1,%2,%3}, {%4,%5,%6,%7}, {%8,%9}, {%0,%1,%2,%3};\n"
        : "+f"(c[0]), "+f"(c[1]), "+f"(c[2]), "+f"(c[3])
        : "r"(a[0]), "r"(a[1]), "r"(a[2]), "r"(a[3]), "r"(b0), "r"(b1));
}

__device__ __forceinline__ void ldsm_x4(unsigned& r0, unsigned& r1, unsigned& r2, unsigned& r3, unsigned a)
{
    asm volatile("ldmatrix.sync.aligned.m8n8.x4.shared.b16 {%0,%1,%2,%3}, [%4];"
        : "=r"(r0), "=r"(r1), "=r"(r2), "=r"(r3) : "r"(a));
}
__device__ __forceinline__ void ldsm_x4t(unsigned& r0, unsigned& r1, unsigned& r2, unsigned& r3, unsigned a)
{
    asm volatile("ldmatrix.sync.aligned.m8n8.x4.trans.shared.b16 {%0,%1,%2,%3}, [%4];"
        : "=r"(r0), "=r"(r1), "=r"(r2), "=r"(r3) : "r"(a));
}
__device__ __forceinline__ void cp16(unsigned dst, const void* src)
{
    asm volatile("cp.async.cg.shared.global [%0], [%1], 16;" :: "r"(dst), "l"(src));
}
#define CP_COMMIT() asm volatile("cp.async.commit_group;" ::: "memory")

// ---------------------------------------------------------------------------
// conversion kernels
// ---------------------------------------------------------------------------
__global__ void conv_x_kernel(const float* __restrict__ x,
                              __nv_bfloat16* __restrict__ xh, __nv_bfloat16* __restrict__ xl)
{
    size_t i = ((size_t)blockIdx.x * 256 + threadIdx.x) * 4;
    float4 v = *(const float4*)(x + i);
    unsigned h0, l0, h1, l1;
    pack_split(v.x, v.y, h0, l0);
    pack_split(v.z, v.w, h1, l1);
    *(uint2*)(xh + i) = make_uint2(h0, h1);
    *(uint2*)(xl + i) = make_uint2(l0, l1);
}

// W[K,N] fp32 -> Wt[N,K] bf16 hi/lo (transpose via smem)
__global__ void conv_wt_kernel(const float* __restrict__ W,
                               __nv_bfloat16* __restrict__ wh, __nv_bfloat16* __restrict__ wl)
{
    __shared__ float t[32][33];
    int k0 = blockIdx.x * 32, n0 = blockIdx.y * 32;
    int tx = threadIdx.x, ty = threadIdx.y;
    #pragma unroll
    for (int i = 0; i < 4; i++)
        t[ty + 8*i][tx] = W[(size_t)(k0 + ty + 8*i) * CC + n0 + tx];
    __syncthreads();
    #pragma unroll
    for (int i = 0; i < 4; i++) {
        int n = n0 + ty + 8*i, k = k0 + tx;
        float v = t[tx][ty + 8*i];
        __nv_bfloat16 h = __float2bfloat16(v);
        wh[(size_t)n * CC + k] = h;
        wl[(size_t)n * CC + k] = __float2bfloat16(v - __bfloat162float(h));
    }
}

// ---------------------------------------------------------------------------
// GEMM v2: C = A @ B^T(+bias). A: [M,K] bf16 hi/lo; B: [N,K] bf16 hi/lo.
// cp.async double-buffered, tile 128x128x16, R7-proven fragment scheme.
// mode 0: fp32 row-major out; mode 1: bf16 hi/lo out permuted [B,H,T,D].
// ---------------------------------------------------------------------------
__global__ __launch_bounds__(256, 2) void gemm2_kernel(
    const __nv_bfloat16* __restrict__ Ah, const __nv_bfloat16* __restrict__ Al,
    const __nv_bfloat16* __restrict__ Bh, const __nv_bfloat16* __restrict__ Bl,
    const float* __restrict__ bias, float* __restrict__ outf,
    __nv_bfloat16* __restrict__ outh, __nv_bfloat16* __restrict__ outl, int mode)
{
    __shared__ unsigned short As_h[2][128*SROW], As_l[2][128*SROW];
    __shared__ unsigned short Bs_h[2][128*SROW], Bs_l[2][128*SROW];

    const int K = CC, N = CC;
    int tid = threadIdx.x, warp = tid >> 5, lane = tid & 31;
    int g = lane >> 2, tg = lane & 3;
    int wm = (warp >> 2) << 6, wn = (warp & 3) << 5;
    int m0 = blockIdx.y << 7, n0 = blockIdx.x << 7;
    int rld = tid & 127, kh = tid >> 7;

    const __nv_bfloat16* ApH = Ah + (size_t)(m0 + rld) * K + kh * 8;
    const __nv_bfloat16* ApL = Al + (size_t)(m0 + rld) * K + kh * 8;
    const __nv_bfloat16* BpH = Bh + (size_t)(n0 + rld) * K + kh * 8;
    const __nv_bfloat16* BpL = Bl + (size_t)(n0 + rld) * K + kh * 8;

    unsigned bAh = (unsigned)__cvta_generic_to_shared(&As_h[0][0]);
    unsigned bAl = (unsigned)__cvta_generic_to_shared(&As_l[0][0]);
    unsigned bBh = (unsigned)__cvta_generic_to_shared(&Bs_h[0][0]);
    unsigned bBl = (unsigned)__cvta_generic_to_shared(&Bs_l[0][0]);
    unsigned doff = (rld * SROW + kh * 8) * 2;   // byte offset within stage

    float c[4][4][4];
    #pragma unroll
    for (int mf = 0; mf < 4; mf++)
        #pragma unroll
        for (int nf = 0; nf < 4; nf++)
            #pragma unroll
            for (int i = 0; i < 4; i++) c[mf][nf][i] = 0.0f;

    // stage 0
    {
        cp16(bAh + doff, ApH); cp16(bAl + doff, ApL);
        cp16(bBh + doff, BpH); cp16(bBl + doff, BpL);
        CP_COMMIT();
    }

    #pragma unroll 1
    for (int it = 0; it < K / 16; it++) {
        if (it + 1 < K / 16) {
            unsigned so = ((it + 1) & 1) * (128 * SROW * 2);
            int ko = (it + 1) * 16;
            cp16(bAh + so + doff, ApH + ko); cp16(bAl + so + doff, ApL + ko);
            cp16(bBh + so + doff, BpH + ko); cp16(bBl + so + doff, BpL + ko);
            CP_COMMIT();
            asm volatile("cp.async.wait_group 1;" ::: "memory");
        } else {
            asm volatile("cp.async.wait_group 0;" ::: "memory");
        }
        __syncthreads();

        const unsigned short* ash = As_h[it & 1];
        const unsigned short* asl = As_l[it & 1];
        const unsigned short* bsh = Bs_h[it & 1];
        const unsigned short* bsl = Bs_l[it & 1];

        unsigned ahi[4][4], alo[4][4];
        #pragma unroll
        for (int mf = 0; mf < 4; mf++) {
            int r = wm + mf*16 + g;
            int b0 = r * SROW, b8 = (r + 8) * SROW;
            ahi[mf][0] = *(const unsigned*)&ash[b0 + 2*tg];
            ahi[mf][1] = *(const unsigned*)&ash[b8 + 2*tg];
            ahi[mf][2] = *(const unsigned*)&ash[b0 + 2*tg + 8];
            ahi[mf][3] = *(const unsigned*)&ash[b8 + 2*tg + 8];
            alo[mf][0] = *(const unsigned*)&asl[b0 + 2*tg];
            alo[mf][1] = *(const unsigned*)&asl[b8 + 2*tg];
            alo[mf][2] = *(const unsigned*)&asl[b0 + 2*tg + 8];
            alo[mf][3] = *(const unsigned*)&asl[b8 + 2*tg + 8];
        }
        #pragma unroll
        for (int nf = 0; nf < 4; nf++) {
            int cb = (wn + nf*8 + g) * SROW;
            unsigned bh0 = *(const unsigned*)&bsh[cb + 2*tg];
            unsigned bh1 = *(const unsigned*)&bsh[cb + 2*tg + 8];
            unsigned bl0 = *(const unsigned*)&bsl[cb + 2*tg];
            unsigned bl1 = *(const unsigned*)&bsl[cb + 2*tg + 8];
            #pragma unroll
            for (int mf = 0; mf < 4; mf++) {
                mma_bf16(c[mf][nf], ahi[mf], bh0, bh1);
                mma_bf16(c[mf][nf], ahi[mf], bl0, bl1);
                mma_bf16(c[mf][nf], alo[mf], bh0, bh1);
            }
        }
        __syncthreads();
    }

    #pragma unroll
    for (int mf = 0; mf < 4; mf++) {
        #pragma unroll
        for (int nf = 0; nf < 4; nf++) {
            int r  = m0 + wm + mf*16 + g;
            int cc = n0 + wn + nf*8 + 2*tg;
            float2 bb = *(const float2*)&bias[cc];
            float p0x = c[mf][nf][0] + bb.x, p0y = c[mf][nf][1] + bb.y;
            float p1x = c[mf][nf][2] + bb.x, p1y = c[mf][nf][3] + bb.y;
            if (mode == 0) {
                *(float2*)&outf[(size_t)r * N + cc]       = make_float2(p0x, p0y);
                *(float2*)&outf[(size_t)(r + 8) * N + cc] = make_float2(p1x, p1y);
            } else {
                int h = cc >> 6, d = cc & 63;
                int b1 = r >> 11, t1 = r & (TT - 1);
                size_t i0 = ((size_t)(((b1 << 4) + h) * TT + t1) << 6) + d;
                unsigned ph, pl;
                pack_split(p0x, p0y, ph, pl);
                *(unsigned*)&outh[i0] = ph;  *(unsigned*)&outl[i0] = pl;
                int r2 = r + 8;
                int b2 = r2 >> 11, t2 = r2 & (TT - 1);
                size_t i1 = ((size_t)(((b2 << 4) + h) * TT + t2) << 6) + d;
                pack_split(p1x, p1y, ph, pl);
                *(unsigned*)&outh[i1] = ph;  *(unsigned*)&outl[i1] = pl;
            }
        }
    }
}

// ---------------------------------------------------------------------------
// Tensor-core flash attention. 128 threads, 4 warps; warp w owns q-rows
// [w*16, w*16+16) x all 64 cols. Split-bf16 (3-pass) QK^T and PV mma.
// K/V tiles double-buffered via cp.async; S c-frags reused as P a-frags.
// ---------------------------------------------------------------------------
__device__ __forceinline__ void attn_issue_kv(unsigned sbase, int bh, int jb, int st, int tid)
{
    const int OKH = 9216, OKL = 18432, OVH = 27648, OVL = 36864;  // ush units
    size_t gb = ((size_t)bh * TT + (size_t)jb * 64) * 64;
    #pragma unroll
    for (int i = 0; i < 4; i++) {
        int cc = i * 128 + tid;
        int row = cc >> 3, ch = cc & 7;
        unsigned so = (row * AROW + ch * 8) * 2;
        size_t  go = gb + row * 64 + ch * 8;
        cp16(sbase + (OKH + st*4608)*2 + so, g_kh + go);
        cp16(sbase + (OKL + st*4608)*2 + so, g_kl + go);
        cp16(sbase + (OVH + st*4608)*2 + so, g_vh + go);
        cp16(sbase + (OVL + st*4608)*2 + so, g_vl + go);
    }
    CP_COMMIT();
}

__global__ __launch_bounds__(128) void attn2_kernel()
{
    extern __shared__ unsigned short sm2[];
    const int OQH = 0, OQL = 4608, OKH = 9216, OKL = 18432, OVH = 27648, OVL = 36864;

    int tid = threadIdx.x, w = tid >> 5, lane = tid & 31;
    int g = lane >> 2, tg = lane & 3;
    int qb = blockIdx.x, bh = blockIdx.y;
    unsigned sbase = (unsigned)__cvta_generic_to_shared(sm2);

    // load Q tile (hi/lo)
    {
        size_t gb = ((size_t)bh * TT + (size_t)qb * 64) * 64;
        #pragma unroll
        for (int i = 0; i < 4; i++) {
            int cc = i * 128 + tid;
            int row = cc >> 3, ch = cc & 7;
            unsigned so = (row * AROW + ch * 8) * 2;
            cp16(sbase + OQH*2 + so, g_qh + gb + row * 64 + ch * 8);
            cp16(sbase + OQL*2 + so, g_ql + gb + row * 64 + ch * 8);
        }
        CP_COMMIT();
        asm volatile("cp.async.wait_group 0;" ::: "memory");
        __syncthreads();
    }

    // Q a-frags (resident): row = w*16 + (lane&15), koff = kk*16 + (lane>>4)*8
    unsigned qa_h[4][4], qa_l[4][4];
    {
        int r = w * 16 + (lane & 15);
        #pragma unroll
        for (int kk = 0; kk < 4; kk++) {
            int koff = kk * 16 + (lane >> 4) * 8;
            unsigned ad = (r * AROW + koff) * 2;
            ldsm_x4(qa_h[kk][0], qa_h[kk][1], qa_h[kk][2], qa_h[kk][3], sbase + OQH*2 + ad);
            ldsm_x4(qa_l[kk][0], qa_l[kk][1], qa_l[kk][2], qa_l[kk][3], sbase + OQL*2 + ad);
        }
    }

    attn_issue_kv(sbase, bh, 0, 0, tid);

    float m_r[2] = {-1e30f, -1e30f}, l_r[2] = {0.0f, 0.0f};
    float o[8][4];
    #pragma unroll
    for (int nf = 0; nf < 8; nf++)
        #pragma unroll
        for (int i = 0; i < 4; i++) o[nf][i] = 0.0f;

    // ldmatrix lane-address components
    int kn_row = ((lane >> 4) & 1) * 8 + (lane & 7);   // K: n-row within 16
    int kn_ko  = ((lane >> 3) & 1) * 8;                // K: k offset within 16
    int v_sr   = ((lane >> 3) & 1) * 8 + (lane & 7);   // V: s-row within 16
    int v_dc   = ((lane >> 4) & 1) * 8;                // V: d offset within 16

    #pragma unroll 1
    for (int jb = 0; jb <= qb; jb++) {
        int st = jb & 1;
        if (jb < qb) {
            attn_issue_kv(sbase, bh, jb + 1, st ^ 1, tid);
            asm volatile("cp.async.wait_group 1;" ::: "memory");
        } else {
            asm volatile("cp.async.wait_group 0;" ::: "memory");
        }
        __syncthreads();

        // ---- S = Q @ K^T (split bf16, 3 passes) ----
        float sc[8][4];
        #pragma unroll
        for (int nf = 0; nf < 8; nf++)
            #pragma unroll
            for (int i = 0; i < 4; i++) sc[nf][i] = 0.0f;

        #pragma unroll
        for (int kk = 0; kk < 4; kk++) {
            int koff = kk * 16 + kn_ko;
            #pragma unroll
            for (int p = 0; p < 4; p++) {
                int nr = p * 16 + kn_row;
                unsigned kbh0,kbh1,kbh2,kbh3, kbl0,kbl1,kbl2,kbl3;
                unsigned ad = (nr * AROW + koff) * 2;
                ldsm_x4(kbh0,kbh1,kbh2,kbh3, sbase + (OKH + st*4608)*2 + ad);
                ldsm_x4(kbl0,kbl1,kbl2,kbl3, sbase + (OKL + st*4608)*2 + ad);
                mma_bf16(sc[2*p],   qa_h[kk], kbh0, kbh1);
                mma_bf16(sc[2*p],   qa_h[kk], kbl0, kbl1);
                mma_bf16(sc[2*p],   qa_l[kk], kbh0, kbh1);
                mma_bf16(sc[2*p+1], qa_h[kk], kbh2, kbh3);
                mma_bf16(sc[2*p+1], qa_h[kk], kbl2, kbl3);
                mma_bf16(sc[2*p+1], qa_l[kk], kbh2, kbh3);
            }
        }

        // scale + causal mask
        #pragma unroll
        for (int nf = 0; nf < 8; nf++)
            #pragma unroll
            for (int i = 0; i < 4; i++) sc[nf][i] *= 0.125f;
        if (jb == qb) {
            int r0 = w * 16 + g, r1 = r0 + 8;
            #pragma unroll
            for (int nf = 0; nf < 8; nf++) {
                int c0 = nf * 8 + 2 * tg, c1 = c0 + 1;
                if (c0 > r0) sc[nf][0] = -1e30f;
                if (c1 > r0) sc[nf][1] = -1e30f;
                if (c0 > r1) sc[nf][2] = -1e30f;
                if (c1 > r1) sc[nf][3] = -1e30f;
            }
        }

        // ---- online softmax (rows g, g+8) ----
        float mx0 = -1e30f, mx1 = -1e30f;
        #pragma unroll
        for (int nf = 0; nf < 8; nf++) {
            mx0 = fmaxf(mx0, fmaxf(sc[nf][0], sc[nf][1]));
            mx1 = fmaxf(mx1, fmaxf(sc[nf][2], sc[nf][3]));
        }
        mx0 = fmaxf(mx0, __shfl_xor_sync(0xffffffffu, mx0, 1));
        mx0 = fmaxf(mx0, __shfl_xor_sync(0xffffffffu, mx0, 2));
        mx1 = fmaxf(mx1, __shfl_xor_sync(0xffffffffu, mx1, 1));
        mx1 = fmaxf(mx1, __shfl_xor_sync(0xffffffffu, mx1, 2));
        float mn0 = fmaxf(m_r[0], mx0), mn1 = fmaxf(m_r[1], mx1);
        float cr0 = __expf(m_r[0] - mn0), cr1 = __expf(m_r[1] - mn1);
        m_r[0] = mn0; m_r[1] = mn1;
        float s0 = 0.0f, s1 = 0.0f;
        #pragma unroll
        for (int nf = 0; nf < 8; nf++) {
            sc[nf][0] = __expf(sc[nf][0] - mn0); s0 += sc[nf][0];
            sc[nf][1] = __expf(sc[nf][1] - mn0); s0 += sc[nf][1];
            sc[nf][2] = __expf(sc[nf][2] - mn1); s1 += sc[nf][2];
            sc[nf][3] = __expf(sc[nf][3] - mn1); s1 += sc[nf][3];
        }
        s0 += __shfl_xor_sync(0xffffffffu, s0, 1);
        s0 += __shfl_xor_sync(0xffffffffu, s0, 2);
        s1 += __shfl_xor_sync(0xffffffffu, s1, 1);
        s1 += __shfl_xor_sync(0xffffffffu, s1, 2);
        l_r[0] = l_r[0] * cr0 + s0;
        l_r[1] = l_r[1] * cr1 + s1;
        #pragma unroll
        for (int nf = 0; nf < 8; nf++) {
            o[nf][0] *= cr0; o[nf][1] *= cr0;
            o[nf][2] *= cr1; o[nf][3] *= cr1;
        }

        // ---- O += P @ V (split bf16: Ph*Vh + Ph*Vl + Pl*Vh) ----
        #pragma unroll
        for (int ss = 0; ss < 4; ss++) {
            unsigned ah[4], al[4];
            pack_split(sc[2*ss][0],   sc[2*ss][1],   ah[0], al[0]);
            pack_split(sc[2*ss][2],   sc[2*ss][3],   ah[1], al[1]);
            pack_split(sc[2*ss+1][0], sc[2*ss+1][1], ah[2], al[2]);
            pack_split(sc[2*ss+1][2], sc[2*ss+1][3], ah[3], al[3]);
            int sr = ss * 16 + v_sr;
            #pragma unroll
            for (int p = 0; p < 4; p++) {
                int dc = p * 16 + v_dc;
                unsigned vh0,vh1,vh2,vh3, vl0,vl1,vl2,vl3;
                unsigned ad = (sr * AROW + dc) * 2;
                ldsm_x4t(vh0,vh1,vh2,vh3, sbase + (OVH + st*4608)*2 + ad);
                ldsm_x4t(vl0,vl1,vl2,vl3, sbase + (OVL + st*4608)*2 + ad);
                mma_bf16(o[2*p],   ah, vh0, vh1);
                mma_bf16(o[2*p],   ah, vl0, vl1);
                mma_bf16(o[2*p],   al, vh0, vh1);
                mma_bf16(o[2*p+1], ah, vh2, vh3);
                mma_bf16(o[2*p+1], ah, vl2, vl3);
                mma_bf16(o[2*p+1], al, vh2, vh3);
            }
        }
        __syncthreads();
    }

    // epilogue: normalize + write y as bf16 hi/lo  [B,T,C]
    int b = bh >> 4, h = bh & 15;
    int t0 = qb * 64 + w * 16 + g, t1 = t0 + 8;
    float inv0 = 1.0f / l_r[0], inv1 = 1.0f / l_r[1];
    size_t r0 = ((size_t)(b * TT + t0) << 10) + (h << 6);
    size_t r1 = ((size_t)(b * TT + t1) << 10) + (h << 6);
    #pragma unroll
    for (int nf = 0; nf < 8; nf++) {
        int col = nf * 8 + 2 * tg;
        unsigned ph, pl;
        pack_split(o[nf][0] * inv0, o[nf][1] * inv0, ph, pl);
        *(unsigned*)&g_yh[r0 + col] = ph;  *(unsigned*)&g_yl[r0 + col] = pl;
        pack_split(o[nf][2] * inv1, o[nf][3] * inv1, ph, pl);
        *(unsigned*)&g_yh[r1 + col] = ph;  *(unsigned*)&g_yl[r1 + col] = pl;
    }
}

// ---------------------------------------------------------------------------

extern "C" void kernel_launch(void* const* d_in, const int* in_sizes, int n_in,
                              void* d_out, int out_size)
{
    (void)in_sizes; (void)n_in; (void)out_size;
    const float* x  = (const float*)d_in[0];
    const float* Wq = (const float*)d_in[1];
    const float* bq = (const float*)d_in[2];
    const float* Wk = (const float*)d_in[3];
    const float* bk = (const float*)d_in[4];
    const float* Wv = (const float*)d_in[5];
    const float* bv = (const float*)d_in[6];
    const float* Wp = (const float*)d_in[7];
    const float* bp = (const float*)d_in[8];

    __nv_bfloat16 *xh, *xl, *wth, *wtl, *qh, *ql, *kh, *kl, *vh, *vl, *yh, *yl;
    cudaGetSymbolAddress((void**)&xh, g_xh);   cudaGetSymbolAddress((void**)&xl, g_xl);
    cudaGetSymbolAddress((void**)&wth, g_wth); cudaGetSymbolAddress((void**)&wtl, g_wtl);
    cudaGetSymbolAddress((void**)&qh, g_qh);   cudaGetSymbolAddress((void**)&ql, g_ql);
    cudaGetSymbolAddress((void**)&kh, g_kh);   cudaGetSymbolAddress((void**)&kl, g_kl);
    cudaGetSymbolAddress((void**)&vh, g_vh);   cudaGetSymbolAddress((void**)&vl, g_vl);
    cudaGetSymbolAddress((void**)&yh, g_yh);   cudaGetSymbolAddress((void**)&yl, g_yl);

    const int attn_smem = 10 * 64 * AROW * 2;   // 92160 B
    cudaFuncSetAttribute(attn2_kernel, cudaFuncAttributeMaxDynamicSharedMemorySize, attn_smem);

    // conversions
    conv_x_kernel<<<MM*CC/1024, 256>>>(x, xh, xl);
    dim3 wtg(CC/32, CC/32), wtb(32, 8);
    conv_wt_kernel<<<wtg, wtb>>>(Wq, wth + 0*CC*CC, wtl + 0*CC*CC);
    conv_wt_kernel<<<wtg, wtb>>>(Wk, wth + 1*CC*CC, wtl + 1*CC*CC);
    conv_wt_kernel<<<wtg, wtb>>>(Wv, wth + 2*CC*CC, wtl + 2*CC*CC);
    conv_wt_kernel<<<wtg, wtb>>>(Wp, wth + 3*CC*CC, wtl + 3*CC*CC);

    dim3 gg(CC/128, MM/128);   // (8, 64)
    gemm2_kernel<<<gg, 256>>>(xh, xl, wth + 0*CC*CC, wtl + 0*CC*CC, bq, nullptr, qh, ql, 1);
    gemm2_kernel<<<gg, 256>>>(xh, xl, wth + 1*CC*CC, wtl + 1*CC*CC, bk, nullptr, kh, kl, 1);
    gemm2_kernel<<<gg, 256>>>(xh, xl, wth + 2*CC*CC, wtl + 2*CC*CC, bv, nullptr, vh, vl, 1);

    attn2_kernel<<<dim3(TT/64, NB*NH), 128, attn_smem>>>();

    gemm2_kernel<<<gg, 256>>>(yh, yl, wth + 3*CC*CC, wtl + 3*CC*CC, bp, (float*)d_out, nullptr, nullptr, 0);
}

// round 9
// speedup vs baseline: 2.2659x; 1.0402x over previous
#include <cuda_runtime.h>
#include <cuda_bf16.h>
#include <math.h>

#define NB 4
#define NH 16
#define TT 2048
#define DD 64
#define CC 1024
#define MM (NB*TT)   // 8192
#define SROW 24      // gemm smem row stride (bf16)
#define AROW 72      // attn smem row stride (bf16)

// ---- device scratch (no allocs allowed) ----
__device__ __nv_bfloat16 g_xh[MM*CC],  g_xl[MM*CC];
__device__ __nv_bfloat16 g_wth[4*CC*CC], g_wtl[4*CC*CC];   // transposed [N][K] per weight
__device__ __nv_bfloat16 g_qh[MM*CC],  g_ql[MM*CC];
__device__ __nv_bfloat16 g_kh[MM*CC],  g_kl[MM*CC];
__device__ __nv_bfloat16 g_vh[MM*CC],  g_vl[MM*CC];
__device__ __nv_bfloat16 g_yh[MM*CC],  g_yl[MM*CC];

// ---- helpers ----
__device__ __forceinline__ void pack_split(float x0, float x1, unsigned& h, unsigned& l)
{
    __nv_bfloat16 h0 = __float2bfloat16(x0);
    __nv_bfloat16 h1 = __float2bfloat16(x1);
    __nv_bfloat16 l0 = __float2bfloat16(x0 - __bfloat162float(h0));
    __nv_bfloat16 l1 = __float2bfloat16(x1 - __bfloat162float(h1));
    h = (unsigned)__bfloat16_as_ushort(h0) | ((unsigned)__bfloat16_as_ushort(h1) << 16);
    l = (unsigned)__bfloat16_as_ushort(l0) | ((unsigned)__bfloat16_as_ushort(l1) << 16);
}

__device__ __forceinline__ void mma_bf16(float* c, const unsigned* a, unsigned b0, unsigned b1)
{
    asm volatile(
        "mma.sync.aligned.m16n8k16.row.col.f32.bf16.bf16.f32 "
        "{%0,%1,%2,%3}, {%4,%5,%6,%7}, {%8,%9}, {%0,%1,%2,%3};\n"
        : "+f"(c[0]), "+f"(c[1]), "+f"(c[2]), "+f"(c[3])
        : "r"(a[0]), "r"(a[1]), "r"(a[2]), "r"(a[3]), "r"(b0), "r"(b1));
}

__device__ __forceinline__ void ldsm_x4(unsigned& r0, unsigned& r1, unsigned& r2, unsigned& r3, unsigned a)
{
    asm volatile("ldmatrix.sync.aligned.m8n8.x4.shared.b16 {%0,%1,%2,%3}, [%4];"
        : "=r"(r0), "=r"(r1), "=r"(r2), "=r"(r3) : "r"(a));
}
__device__ __forceinline__ void ldsm_x4t(unsigned& r0, unsigned& r1, unsigned& r2, unsigned& r3, unsigned a)
{
    asm volatile("ldmatrix.sync.aligned.m8n8.x4.trans.shared.b16 {%0,%1,%2,%3}, [%4];"
        : "=r"(r0), "=r"(r1), "=r"(r2), "=r"(r3) : "r"(a));
}
__device__ __forceinline__ void cp16(unsigned dst, const void* src)
{
    asm volatile("cp.async.cg.shared.global [%0], [%1], 16;" :: "r"(dst), "l"(src));
}
#define CP_COMMIT() asm volatile("cp.async.commit_group;" ::: "memory")

// ---------------------------------------------------------------------------
// conversion kernels
// ---------------------------------------------------------------------------
__global__ void conv_x_kernel(const float* __restrict__ x,
                              __nv_bfloat16* __restrict__ xh, __nv_bfloat16* __restrict__ xl)
{
    size_t i = ((size_t)blockIdx.x * 256 + threadIdx.x) * 4;
    float4 v = *(const float4*)(x + i);
    unsigned h0, l0, h1, l1;
    pack_split(v.x, v.y, h0, l0);
    pack_split(v.z, v.w, h1, l1);
    *(uint2*)(xh + i) = make_uint2(h0, h1);
    *(uint2*)(xl + i) = make_uint2(l0, l1);
}

// W[K,N] fp32 -> Wt[N,K] bf16 hi/lo (transpose via smem)
__global__ void conv_wt_kernel(const float* __restrict__ W,
                               __nv_bfloat16* __restrict__ wh, __nv_bfloat16* __restrict__ wl)
{
    __shared__ float t[32][33];
    int k0 = blockIdx.x * 32, n0 = blockIdx.y * 32;
    int tx = threadIdx.x, ty = threadIdx.y;
    #pragma unroll
    for (int i = 0; i < 4; i++)
        t[ty + 8*i][tx] = W[(size_t)(k0 + ty + 8*i) * CC + n0 + tx];
    __syncthreads();
    #pragma unroll
    for (int i = 0; i < 4; i++) {
        int n = n0 + ty + 8*i, k = k0 + tx;
        float v = t[tx][ty + 8*i];
        __nv_bfloat16 h = __float2bfloat16(v);
        wh[(size_t)n * CC + k] = h;
        wl[(size_t)n * CC + k] = __float2bfloat16(v - __bfloat162float(h));
    }
}

// ---------------------------------------------------------------------------
// GEMM v3: C = A @ B^T(+bias). A: [M,K] bf16 hi/lo; B: [N,K] bf16 hi/lo.
// cp.async double-buffered, tile 128x128x16; fragments via ldmatrix.x4
// (12 LDSM vs 48 LDS.32 per warp per k-iter in v2).
// mode 0: fp32 row-major out; mode 1: bf16 hi/lo out permuted [B,H,T,D].
// ---------------------------------------------------------------------------
__global__ __launch_bounds__(256, 2) void gemm3_kernel(
    const __nv_bfloat16* __restrict__ Ah, const __nv_bfloat16* __restrict__ Al,
    const __nv_bfloat16* __restrict__ Bh, const __nv_bfloat16* __restrict__ Bl,
    const float* __restrict__ bias, float* __restrict__ outf,
    __nv_bfloat16* __restrict__ outh, __nv_bfloat16* __restrict__ outl, int mode)
{
    __shared__ unsigned short As_h[2][128*SROW], As_l[2][128*SROW];
    __shared__ unsigned short Bs_h[2][128*SROW], Bs_l[2][128*SROW];

    const int K = CC, N = CC;
    int tid = threadIdx.x, warp = tid >> 5, lane = tid & 31;
    int g = lane >> 2, tg = lane & 3;
    int wm = (warp >> 2) << 6, wn = (warp & 3) << 5;
    int m0 = blockIdx.y << 7, n0 = blockIdx.x << 7;
    int rld = tid & 127, kh = tid >> 7;

    // ldmatrix lane addressing (proven in R8 attention kernel)
    int a_row = lane & 15;                               // A: row within 16-group
    int a_ko  = (lane >> 4) * 8;                         // A: k offset
    int b_row = ((lane >> 4) & 1) * 8 + (lane & 7);      // B: n-row within 16
    int b_ko  = ((lane >> 3) & 1) * 8;                   // B: k offset

    const __nv_bfloat16* ApH = Ah + (size_t)(m0 + rld) * K + kh * 8;
    const __nv_bfloat16* ApL = Al + (size_t)(m0 + rld) * K + kh * 8;
    const __nv_bfloat16* BpH = Bh + (size_t)(n0 + rld) * K + kh * 8;
    const __nv_bfloat16* BpL = Bl + (size_t)(n0 + rld) * K + kh * 8;

    unsigned bAh = (unsigned)__cvta_generic_to_shared(&As_h[0][0]);
    unsigned bAl = (unsigned)__cvta_generic_to_shared(&As_l[0][0]);
    unsigned bBh = (unsigned)__cvta_generic_to_shared(&Bs_h[0][0]);
    unsigned bBl = (unsigned)__cvta_generic_to_shared(&Bs_l[0][0]);
    unsigned doff = (rld * SROW + kh * 8) * 2;

    float c[4][4][4];
    #pragma unroll
    for (int mf = 0; mf < 4; mf++)
        #pragma unroll
        for (int nf = 0; nf < 4; nf++)
            #pragma unroll
            for (int i = 0; i < 4; i++) c[mf][nf][i] = 0.0f;

    cp16(bAh + doff, ApH); cp16(bAl + doff, ApL);
    cp16(bBh + doff, BpH); cp16(bBl + doff, BpL);
    CP_COMMIT();

    #pragma unroll 1
    for (int it = 0; it < K / 16; it++) {
        if (it + 1 < K / 16) {
            unsigned so = ((it + 1) & 1) * (128 * SROW * 2);
            int ko = (it + 1) * 16;
            cp16(bAh + so + doff, ApH + ko); cp16(bAl + so + doff, ApL + ko);
            cp16(bBh + so + doff, BpH + ko); cp16(bBl + so + doff, BpL + ko);
            CP_COMMIT();
            asm volatile("cp.async.wait_group 1;" ::: "memory");
        } else {
            asm volatile("cp.async.wait_group 0;" ::: "memory");
        }
        __syncthreads();

        unsigned stg = (it & 1) * (128 * SROW * 2);
        unsigned ah[4][4], al[4][4];
        #pragma unroll
        for (int mf = 0; mf < 4; mf++) {
            unsigned ad = stg + ((wm + mf*16 + a_row) * SROW + a_ko) * 2;
            ldsm_x4(ah[mf][0], ah[mf][1], ah[mf][2], ah[mf][3], bAh + ad);
            ldsm_x4(al[mf][0], al[mf][1], al[mf][2], al[mf][3], bAl + ad);
        }
        #pragma unroll
        for (int p = 0; p < 2; p++) {
            unsigned bd = stg + ((wn + p*16 + b_row) * SROW + b_ko) * 2;
            unsigned bh0,bh1,bh2,bh3, bl0,bl1,bl2,bl3;
            ldsm_x4(bh0, bh1, bh2, bh3, bBh + bd);
            ldsm_x4(bl0, bl1, bl2, bl3, bBl + bd);
            #pragma unroll
            for (int mf = 0; mf < 4; mf++) {
                mma_bf16(c[mf][2*p],   ah[mf], bh0, bh1);
                mma_bf16(c[mf][2*p],   ah[mf], bl0, bl1);
                mma_bf16(c[mf][2*p],   al[mf], bh0, bh1);
                mma_bf16(c[mf][2*p+1], ah[mf], bh2, bh3);
                mma_bf16(c[mf][2*p+1], ah[mf], bl2, bl3);
                mma_bf16(c[mf][2*p+1], al[mf], bh2, bh3);
            }
        }
        __syncthreads();
    }

    #pragma unroll
    for (int mf = 0; mf < 4; mf++) {
        #pragma unroll
        for (int nf = 0; nf < 4; nf++) {
            int r  = m0 + wm + mf*16 + g;
            int cc = n0 + wn + nf*8 + 2*tg;
            float2 bb = *(const float2*)&bias[cc];
            float p0x = c[mf][nf][0] + bb.x, p0y = c[mf][nf][1] + bb.y;
            float p1x = c[mf][nf][2] + bb.x, p1y = c[mf][nf][3] + bb.y;
            if (mode == 0) {
                *(float2*)&outf[(size_t)r * N + cc]       = make_float2(p0x, p0y);
                *(float2*)&outf[(size_t)(r + 8) * N + cc] = make_float2(p1x, p1y);
            } else {
                int h = cc >> 6, d = cc & 63;
                int b1 = r >> 11, t1 = r & (TT - 1);
                size_t i0 = ((size_t)(((b1 << 4) + h) * TT + t1) << 6) + d;
                unsigned ph, pl;
                pack_split(p0x, p0y, ph, pl);
                *(unsigned*)&outh[i0] = ph;  *(unsigned*)&outl[i0] = pl;
                int r2 = r + 8;
                int b2 = r2 >> 11, t2 = r2 & (TT - 1);
                size_t i1 = ((size_t)(((b2 << 4) + h) * TT + t2) << 6) + d;
                pack_split(p1x, p1y, ph, pl);
                *(unsigned*)&outh[i1] = ph;  *(unsigned*)&outl[i1] = pl;
            }
        }
    }
}

// ---------------------------------------------------------------------------
// Tensor-core flash attention (R8-proven), plus diagonal-block skips:
// on jb==qb, QK n-groups p>w are fully masked and PV s-groups ss>w have
// all-zero P -> both skipped (exact no-ops numerically).
// ---------------------------------------------------------------------------
__device__ __forceinline__ void attn_issue_kv(unsigned sbase, int bh, int jb, int st, int tid)
{
    const int OKH = 9216, OKL = 18432, OVH = 27648, OVL = 36864;  // ush units
    size_t gb = ((size_t)bh * TT + (size_t)jb * 64) * 64;
    #pragma unroll
    for (int i = 0; i < 4; i++) {
        int cc = i * 128 + tid;
        int row = cc >> 3, ch = cc & 7;
        unsigned so = (row * AROW + ch * 8) * 2;
        size_t  go = gb + row * 64 + ch * 8;
        cp16(sbase + (OKH + st*4608)*2 + so, g_kh + go);
        cp16(sbase + (OKL + st*4608)*2 + so, g_kl + go);
        cp16(sbase + (OVH + st*4608)*2 + so, g_vh + go);
        cp16(sbase + (OVL + st*4608)*2 + so, g_vl + go);
    }
    CP_COMMIT();
}

__global__ __launch_bounds__(128) void attn2_kernel()
{
    extern __shared__ unsigned short sm2[];
    const int OQH = 0, OQL = 4608, OKH = 9216, OKL = 18432, OVH = 27648, OVL = 36864;

    int tid = threadIdx.x, w = tid >> 5, lane = tid & 31;
    int g = lane >> 2, tg = lane & 3;
    int qb = blockIdx.x, bh = blockIdx.y;
    unsigned sbase = (unsigned)__cvta_generic_to_shared(sm2);

    {
        size_t gb = ((size_t)bh * TT + (size_t)qb * 64) * 64;
        #pragma unroll
        for (int i = 0; i < 4; i++) {
            int cc = i * 128 + tid;
            int row = cc >> 3, ch = cc & 7;
            unsigned so = (row * AROW + ch * 8) * 2;
            cp16(sbase + OQH*2 + so, g_qh + gb + row * 64 + ch * 8);
            cp16(sbase + OQL*2 + so, g_ql + gb + row * 64 + ch * 8);
        }
        CP_COMMIT();
        asm volatile("cp.async.wait_group 0;" ::: "memory");
        __syncthreads();
    }

    unsigned qa_h[4][4], qa_l[4][4];
    {
        int r = w * 16 + (lane & 15);
        #pragma unroll
        for (int kk = 0; kk < 4; kk++) {
            int koff = kk * 16 + (lane >> 4) * 8;
            unsigned ad = (r * AROW + koff) * 2;
            ldsm_x4(qa_h[kk][0], qa_h[kk][1], qa_h[kk][2], qa_h[kk][3], sbase + OQH*2 + ad);
            ldsm_x4(qa_l[kk][0], qa_l[kk][1], qa_l[kk][2], qa_l[kk][3], sbase + OQL*2 + ad);
        }
    }

    attn_issue_kv(sbase, bh, 0, 0, tid);

    float m_r[2] = {-1e30f, -1e30f}, l_r[2] = {0.0f, 0.0f};
    float o[8][4];
    #pragma unroll
    for (int nf = 0; nf < 8; nf++)
        #pragma unroll
        for (int i = 0; i < 4; i++) o[nf][i] = 0.0f;

    int kn_row = ((lane >> 4) & 1) * 8 + (lane & 7);
    int kn_ko  = ((lane >> 3) & 1) * 8;
    int v_sr   = ((lane >> 3) & 1) * 8 + (lane & 7);
    int v_dc   = ((lane >> 4) & 1) * 8;

    #pragma unroll 1
    for (int jb = 0; jb <= qb; jb++) {
        int st = jb & 1;
        if (jb < qb) {
            attn_issue_kv(sbase, bh, jb + 1, st ^ 1, tid);
            asm volatile("cp.async.wait_group 1;" ::: "memory");
        } else {
            asm volatile("cp.async.wait_group 0;" ::: "memory");
        }
        __syncthreads();

        bool diag = (jb == qb);

        // ---- S = Q @ K^T ----
        float sc[8][4];
        #pragma unroll
        for (int nf = 0; nf < 8; nf++)
            #pragma unroll
            for (int i = 0; i < 4; i++) sc[nf][i] = 0.0f;

        #pragma unroll
        for (int p = 0; p < 4; p++) {
            if (diag && p > w) continue;      // fully masked cols
            int nr = p * 16 + kn_row;
            #pragma unroll
            for (int kk = 0; kk < 4; kk++) {
                int koff = kk * 16 + kn_ko;
                unsigned kbh0,kbh1,kbh2,kbh3, kbl0,kbl1,kbl2,kbl3;
                unsigned ad = (nr * AROW + koff) * 2;
                ldsm_x4(kbh0,kbh1,kbh2,kbh3, sbase + (OKH + st*4608)*2 + ad);
                ldsm_x4(kbl0,kbl1,kbl2,kbl3, sbase + (OKL + st*4608)*2 + ad);
                mma_bf16(sc[2*p],   qa_h[kk], kbh0, kbh1);
                mma_bf16(sc[2*p],   qa_h[kk], kbl0, kbl1);
                mma_bf16(sc[2*p],   qa_l[kk], kbh0, kbh1);
                mma_bf16(sc[2*p+1], qa_h[kk], kbh2, kbh3);
                mma_bf16(sc[2*p+1], qa_h[kk], kbl2, kbl3);
                mma_bf16(sc[2*p+1], qa_l[kk], kbh2, kbh3);
            }
        }

        #pragma unroll
        for (int nf = 0; nf < 8; nf++)
            #pragma unroll
            for (int i = 0; i < 4; i++) sc[nf][i] *= 0.125f;
        if (diag) {
            int r0 = w * 16 + g, r1 = r0 + 8;
            #pragma unroll
            for (int nf = 0; nf < 8; nf++) {
                int c0 = nf * 8 + 2 * tg, c1 = c0 + 1;
                if (c0 > r0) sc[nf][0] = -1e30f;
                if (c1 > r0) sc[nf][1] = -1e30f;
                if (c0 > r1) sc[nf][2] = -1e30f;
                if (c1 > r1) sc[nf][3] = -1e30f;
            }
        }

        // ---- online softmax ----
        float mx0 = -1e30f, mx1 = -1e30f;
        #pragma unroll
        for (int nf = 0; nf < 8; nf++) {
            mx0 = fmaxf(mx0, fmaxf(sc[nf][0], sc[nf][1]));
            mx1 = fmaxf(mx1, fmaxf(sc[nf][2], sc[nf][3]));
        }
        mx0 = fmaxf(mx0, __shfl_xor_sync(0xffffffffu, mx0, 1));
        mx0 = fmaxf(mx0, __shfl_xor_sync(0xffffffffu, mx0, 2));
        mx1 = fmaxf(mx1, __shfl_xor_sync(0xffffffffu, mx1, 1));
        mx1 = fmaxf(mx1, __shfl_xor_sync(0xffffffffu, mx1, 2));
        float mn0 = fmaxf(m_r[0], mx0), mn1 = fmaxf(m_r[1], mx1);
        float cr0 = __expf(m_r[0] - mn0), cr1 = __expf(m_r[1] - mn1);
        m_r[0] = mn0; m_r[1] = mn1;
        float s0 = 0.0f, s1 = 0.0f;
        #pragma unroll
        for (int nf = 0; nf < 8; nf++) {
            sc[nf][0] = __expf(sc[nf][0] - mn0); s0 += sc[nf][0];
            sc[nf][1] = __expf(sc[nf][1] - mn0); s0 += sc[nf][1];
            sc[nf][2] = __expf(sc[nf][2] - mn1); s1 += sc[nf][2];
            sc[nf][3] = __expf(sc[nf][3] - mn1); s1 += sc[nf][3];
        }
        s0 += __shfl_xor_sync(0xffffffffu, s0, 1);
        s0 += __shfl_xor_sync(0xffffffffu, s0, 2);
        s1 += __shfl_xor_sync(0xffffffffu, s1, 1);
        s1 += __shfl_xor_sync(0xffffffffu, s1, 2);
        l_r[0] = l_r[0] * cr0 + s0;
        l_r[1] = l_r[1] * cr1 + s1;
        #pragma unroll
        for (int nf = 0; nf < 8; nf++) {
            o[nf][0] *= cr0; o[nf][1] *= cr0;
            o[nf][2] *= cr1; o[nf][3] *= cr1;
        }

        // ---- O += P @ V ----
        #pragma unroll
        for (int ss = 0; ss < 4; ss++) {
            if (diag && ss > w) continue;     // all-zero P frags
            unsigned ah[4], al[4];
            pack_split(sc[2*ss][0],   sc[2*ss][1],   ah[0], al[0]);
            pack_split(sc[2*ss][2],   sc[2*ss][3],   ah[1], al[1]);
            pack_split(sc[2*ss+1][0], sc[2*ss+1][1], ah[2], al[2]);
            pack_split(sc[2*ss+1][2], sc[2*ss+1][3], ah[3], al[3]);
            int sr = ss * 16 + v_sr;
            #pragma unroll
            for (int p = 0; p < 4; p++) {
                int dc = p * 16 + v_dc;
                unsigned vh0,vh1,vh2,vh3, vl0,vl1,vl2,vl3;
                unsigned ad = (sr * AROW + dc) * 2;
                ldsm_x4t(vh0,vh1,vh2,vh3, sbase + (OVH + st*4608)*2 + ad);
                ldsm_x4t(vl0,vl1,vl2,vl3, sbase + (OVL + st*4608)*2 + ad);
                mma_bf16(o[2*p],   ah, vh0, vh1);
                mma_bf16(o[2*p],   ah, vl0, vl1);
                mma_bf16(o[2*p],   al, vh0, vh1);
                mma_bf16(o[2*p+1], ah, vh2, vh3);
                mma_bf16(o[2*p+1], ah, vl2, vl3);
                mma_bf16(o[2*p+1], al, vh2, vh3);
            }
        }
        __syncthreads();
    }

    int b = bh >> 4, h = bh & 15;
    int t0 = qb * 64 + w * 16 + g, t1 = t0 + 8;
    float inv0 = 1.0f / l_r[0], inv1 = 1.0f / l_r[1];
    size_t r0 = ((size_t)(b * TT + t0) << 10) + (h << 6);
    size_t r1 = ((size_t)(b * TT + t1) << 10) + (h << 6);
    #pragma unroll
    for (int nf = 0; nf < 8; nf++) {
        int col = nf * 8 + 2 * tg;
        unsigned ph, pl;
        pack_split(o[nf][0] * inv0, o[nf][1] * inv0, ph, pl);
        *(unsigned*)&g_yh[r0 + col] = ph;  *(unsigned*)&g_yl[r0 + col] = pl;
        pack_split(o[nf][2] * inv1, o[nf][3] * inv1, ph, pl);
        *(unsigned*)&g_yh[r1 + col] = ph;  *(unsigned*)&g_yl[r1 + col] = pl;
    }
}

// ---------------------------------------------------------------------------

extern "C" void kernel_launch(void* const* d_in, const int* in_sizes, int n_in,
                              void* d_out, int out_size)
{
    (void)in_sizes; (void)n_in; (void)out_size;
    const float* x  = (const float*)d_in[0];
    const float* Wq = (const float*)d_in[1];
    const float* bq = (const float*)d_in[2];
    const float* Wk = (const float*)d_in[3];
    const float* bk = (const float*)d_in[4];
    const float* Wv = (const float*)d_in[5];
    const float* bv = (const float*)d_in[6];
    const float* Wp = (const float*)d_in[7];
    const float* bp = (const float*)d_in[8];

    __nv_bfloat16 *xh, *xl, *wth, *wtl, *qh, *ql, *kh, *kl, *vh, *vl, *yh, *yl;
    cudaGetSymbolAddress((void**)&xh, g_xh);   cudaGetSymbolAddress((void**)&xl, g_xl);
    cudaGetSymbolAddress((void**)&wth, g_wth); cudaGetSymbolAddress((void**)&wtl, g_wtl);
    cudaGetSymbolAddress((void**)&qh, g_qh);   cudaGetSymbolAddress((void**)&ql, g_ql);
    cudaGetSymbolAddress((void**)&kh, g_kh);   cudaGetSymbolAddress((void**)&kl, g_kl);
    cudaGetSymbolAddress((void**)&vh, g_vh);   cudaGetSymbolAddress((void**)&vl, g_vl);
    cudaGetSymbolAddress((void**)&yh, g_yh);   cudaGetSymbolAddress((void**)&yl, g_yl);

    const int attn_smem = 10 * 64 * AROW * 2;   // 92160 B
    cudaFuncSetAttribute(attn2_kernel, cudaFuncAttributeMaxDynamicSharedMemorySize, attn_smem);

    conv_x_kernel<<<MM*CC/1024, 256>>>(x, xh, xl);
    dim3 wtg(CC/32, CC/32), wtb(32, 8);
    conv_wt_kernel<<<wtg, wtb>>>(Wq, wth + 0*CC*CC, wtl + 0*CC*CC);
    conv_wt_kernel<<<wtg, wtb>>>(Wk, wth + 1*CC*CC, wtl + 1*CC*CC);
    conv_wt_kernel<<<wtg, wtb>>>(Wv, wth + 2*CC*CC, wtl + 2*CC*CC);
    conv_wt_kernel<<<wtg, wtb>>>(Wp, wth + 3*CC*CC, wtl + 3*CC*CC);

    dim3 gg(CC/128, MM/128);   // (8, 64)
    gemm3_kernel<<<gg, 256>>>(xh, xl, wth + 0*CC*CC, wtl + 0*CC*CC, bq, nullptr, qh, ql, 1);
    gemm3_kernel<<<gg, 256>>>(xh, xl, wth + 1*CC*CC, wtl + 1*CC*CC, bk, nullptr, kh, kl, 1);
    gemm3_kernel<<<gg, 256>>>(xh, xl, wth + 2*CC*CC, wtl + 2*CC*CC, bv, nullptr, vh, vl, 1);

    attn2_kernel<<<dim3(TT/64, NB*NH), 128, attn_smem>>>();

    gemm3_kernel<<<gg, 256>>>(yh, yl, wth + 3*CC*CC, wtl + 3*CC*CC, bp, (float*)d_out, nullptr, nullptr, 0);
}